// round 2
// baseline (speedup 1.0000x reference)
#include <cuda_runtime.h>
#include <cuda_bf16.h>

#define C 4096
#define ROWS_PER_BLOCK 8      // 8 warps, one row each
#define MV_THREADS 256

// Scratch (allocation-free rule: __device__ globals)
__device__ float g_x3[3 * C];    // xk | xv | xr
__device__ float g_kvr[3 * C];   // kk | vv | rr
__device__ float g_rwkv[C];      // r * wkv

// ---------------------------------------------------------------------------
// K1: token-shift mix + new_state copy
// ---------------------------------------------------------------------------
__global__ void mix_kernel(const float* __restrict__ x,
                           const float* __restrict__ state,
                           const float* __restrict__ tmk,
                           const float* __restrict__ tmv,
                           const float* __restrict__ tmr,
                           float* __restrict__ out_new_state /* d_out + C */) {
    int i = blockIdx.x * blockDim.x + threadIdx.x;
    if (i >= C) return;
    float xi = x[i];
    float si = state[i];
    float mk = tmk[i], mv = tmv[i], mr = tmr[i];
    g_x3[i]         = xi * mk + si * (1.0f - mk);
    g_x3[C + i]     = xi * mv + si * (1.0f - mv);
    g_x3[2 * C + i] = xi * mr + si * (1.0f - mr);
    out_new_state[i] = xi;
}

// ---------------------------------------------------------------------------
// Shared matvec body: one warp = one row, 4-wide batched float4 loads with
// 4 independent accumulators (MLP_p1 = 4 DRAM loads in flight per warp).
// W loads use __ldcs (read-once streaming). x comes from smem (conflict-free).
// ---------------------------------------------------------------------------
__device__ __forceinline__ float row_dot(const float4* __restrict__ Wr,
                                         const float4* __restrict__ sx,
                                         int lane) {
    float4 a0 = make_float4(0.f, 0.f, 0.f, 0.f);
    float4 a1 = make_float4(0.f, 0.f, 0.f, 0.f);
    float4 a2 = make_float4(0.f, 0.f, 0.f, 0.f);
    float4 a3 = make_float4(0.f, 0.f, 0.f, 0.f);
#pragma unroll
    for (int j = 0; j < 32; j += 4) {
        float4 w0 = __ldcs(&Wr[lane + (j + 0) * 32]);
        float4 w1 = __ldcs(&Wr[lane + (j + 1) * 32]);
        float4 w2 = __ldcs(&Wr[lane + (j + 2) * 32]);
        float4 w3 = __ldcs(&Wr[lane + (j + 3) * 32]);
        float4 x0 = sx[lane + (j + 0) * 32];
        float4 x1 = sx[lane + (j + 1) * 32];
        float4 x2 = sx[lane + (j + 2) * 32];
        float4 x3 = sx[lane + (j + 3) * 32];
        a0.x = fmaf(w0.x, x0.x, a0.x); a0.y = fmaf(w0.y, x0.y, a0.y);
        a0.z = fmaf(w0.z, x0.z, a0.z); a0.w = fmaf(w0.w, x0.w, a0.w);
        a1.x = fmaf(w1.x, x1.x, a1.x); a1.y = fmaf(w1.y, x1.y, a1.y);
        a1.z = fmaf(w1.z, x1.z, a1.z); a1.w = fmaf(w1.w, x1.w, a1.w);
        a2.x = fmaf(w2.x, x2.x, a2.x); a2.y = fmaf(w2.y, x2.y, a2.y);
        a2.z = fmaf(w2.z, x2.z, a2.z); a2.w = fmaf(w2.w, x2.w, a2.w);
        a3.x = fmaf(w3.x, x3.x, a3.x); a3.y = fmaf(w3.y, x3.y, a3.y);
        a3.z = fmaf(w3.z, x3.z, a3.z); a3.w = fmaf(w3.w, x3.w, a3.w);
    }
    float s = ((a0.x + a0.y) + (a0.z + a0.w))
            + ((a1.x + a1.y) + (a1.z + a1.w))
            + ((a2.x + a2.y) + (a2.z + a2.w))
            + ((a3.x + a3.y) + (a3.z + a3.w));
#pragma unroll
    for (int o = 16; o > 0; o >>= 1)
        s += __shfl_xor_sync(0xFFFFFFFFu, s, o);
    return s;
}

// ---------------------------------------------------------------------------
// K2: three matvecs (kw@xk, vw@xv, rw@xr) -> g_kvr
// ---------------------------------------------------------------------------
__global__ __launch_bounds__(MV_THREADS)
void matvec3_kernel(const float* __restrict__ kw,
                    const float* __restrict__ vw,
                    const float* __restrict__ rw) {
    __shared__ float4 sx[C / 4];   // 16 KB
    int mat = blockIdx.y;
    const float* W    = (mat == 0) ? kw : (mat == 1) ? vw : rw;
    const float* xvec = g_x3 + mat * C;
    float*       ov   = g_kvr + mat * C;

    int tid = threadIdx.x;
    const float4* xv4 = reinterpret_cast<const float4*>(xvec);
#pragma unroll
    for (int j = 0; j < (C / 4) / MV_THREADS; j++)
        sx[tid + j * MV_THREADS] = xv4[tid + j * MV_THREADS];
    __syncthreads();

    int warp = tid >> 5;
    int lane = tid & 31;
    int row  = blockIdx.x * ROWS_PER_BLOCK + warp;

    const float4* Wr = reinterpret_cast<const float4*>(W + (size_t)row * C);
    float s = row_dot(Wr, sx, lane);
    if (lane == 0) ov[row] = s;
}

// ---------------------------------------------------------------------------
// K3: elementwise WKV + state update. Writes new_state_a/b/p, stores r*wkv.
// ---------------------------------------------------------------------------
__global__ void wkv_kernel(const float* __restrict__ state_a,
                           const float* __restrict__ state_b,
                           const float* __restrict__ state_p,
                           const float* __restrict__ time_first,
                           const float* __restrict__ time_decay,
                           float* __restrict__ d_out) {
    int i = blockIdx.x * blockDim.x + threadIdx.x;
    if (i >= C) return;

    float kk = g_kvr[i];
    float vv = g_kvr[C + i];
    float rr = g_kvr[2 * C + i];
    float aa = state_a[i];
    float bb = state_b[i];
    float pp = state_p[i];
    float tf = time_first[i];
    float td = time_decay[i];

    float r = 1.0f / (1.0f + expf(-rr));

    // output accumulators (max-trick)
    float ww = tf + kk;
    float p  = fmaxf(pp, ww);
    float e1 = expf(pp - p);
    float e2 = expf(ww - p);
    float a  = e1 * aa + e2 * vv;
    float b  = e1 * bb + e2;

    // state update
    float ww2 = pp + td;
    float p2  = fmaxf(ww2, kk);
    float f1  = expf(ww2 - p2);
    float f2  = expf(kk - p2);
    float na  = f1 * aa + f2 * vv;
    float nb  = f1 * bb + f2;

    d_out[2 * C + i] = na;   // new_state_a
    d_out[3 * C + i] = nb;   // new_state_b
    d_out[4 * C + i] = p2;   // new_state_p

    g_rwkv[i] = r * (a / b);
}

// ---------------------------------------------------------------------------
// K4: out = ow @ (r*wkv) -> d_out[0:C]
// ---------------------------------------------------------------------------
__global__ __launch_bounds__(MV_THREADS)
void matvec_ow_kernel(const float* __restrict__ ow,
                      float* __restrict__ out /* d_out */) {
    __shared__ float4 sx[C / 4];
    int tid = threadIdx.x;
    const float4* xv4 = reinterpret_cast<const float4*>(g_rwkv);
#pragma unroll
    for (int j = 0; j < (C / 4) / MV_THREADS; j++)
        sx[tid + j * MV_THREADS] = xv4[tid + j * MV_THREADS];
    __syncthreads();

    int warp = tid >> 5;
    int lane = tid & 31;
    int row  = blockIdx.x * ROWS_PER_BLOCK + warp;

    const float4* Wr = reinterpret_cast<const float4*>(ow + (size_t)row * C);
    float s = row_dot(Wr, sx, lane);
    if (lane == 0) out[row] = s;
}

// ---------------------------------------------------------------------------
// Launch. Input order (metadata): x, state, state_a, state_b, state_p,
// time_mix_k, time_mix_v, time_mix_r, time_first, time_decay, kw, vw, rw, ow.
// Output layout: [out | new_state | new_state_a | new_state_b | new_state_p]
// ---------------------------------------------------------------------------
extern "C" void kernel_launch(void* const* d_in, const int* in_sizes, int n_in,
                              void* d_out, int out_size) {
    const float* x   = (const float*)d_in[0];
    const float* st  = (const float*)d_in[1];
    const float* sa  = (const float*)d_in[2];
    const float* sb  = (const float*)d_in[3];
    const float* sp  = (const float*)d_in[4];
    const float* tmk = (const float*)d_in[5];
    const float* tmv = (const float*)d_in[6];
    const float* tmr = (const float*)d_in[7];
    const float* tf  = (const float*)d_in[8];
    const float* td  = (const float*)d_in[9];
    const float* kw  = (const float*)d_in[10];
    const float* vw  = (const float*)d_in[11];
    const float* rw  = (const float*)d_in[12];
    const float* ow  = (const float*)d_in[13];
    float* out = (float*)d_out;

    mix_kernel<<<C / 256, 256>>>(x, st, tmk, tmv, tmr, out + C);

    dim3 g2(C / ROWS_PER_BLOCK, 3);
    matvec3_kernel<<<g2, MV_THREADS>>>(kw, vw, rw);

    wkv_kernel<<<C / 256, 256>>>(sa, sb, sp, tf, td, out);

    matvec_ow_kernel<<<C / ROWS_PER_BLOCK, MV_THREADS>>>(ow, out);
}